// round 2
// baseline (speedup 1.0000x reference)
#include <cuda_runtime.h>

#define N_NODES 100000
#define N_EDGES 3200000
#define IN_DIM 128
#define HID 64
#define OUT_DIM 32
#define N_LAYERS 3

// Scratch: device globals (alloc-free, graph-capture safe)
__device__ float g_hA[N_NODES * HID];
__device__ float g_hB[N_NODES * HID];
__device__ float g_agg[N_NODES * HID];
__device__ int   g_src[N_EDGES];
__device__ int   g_dst[N_EDGES];
__device__ int   g_is64;

// ---------------------------------------------------------------------------
// Detect edge_index dtype. int64 values < 2^31 => odd 32-bit words are 0.
// int32 random values in [0, 100000): some odd word is nonzero w.p. ~1.
// ---------------------------------------------------------------------------
__global__ void detect_kernel(const int* __restrict__ ei_raw) {
    if (threadIdx.x == 0 && blockIdx.x == 0) {
        int is64 = 1;
        for (int i = 0; i < 64; i++)
            if (ei_raw[2 * i + 1] != 0) { is64 = 0; break; }
        g_is64 = is64;
    }
}

// ---------------------------------------------------------------------------
// Edge index conversion -> int32 (done once per call, reused 3 layers)
// ---------------------------------------------------------------------------
__global__ void prep_edges_kernel(const void* __restrict__ ei) {
    int i = blockIdx.x * blockDim.x + threadIdx.x;
    if (i >= N_EDGES) return;
    if (g_is64) {
        const long long* p = (const long long*)ei;
        g_src[i] = (int)p[i];
        g_dst[i] = (int)p[N_EDGES + i];
    } else {
        const int* p = (const int*)ei;
        g_src[i] = p[i];
        g_dst[i] = p[N_EDGES + i];
    }
}

// ---------------------------------------------------------------------------
// Zero the aggregation buffer
// ---------------------------------------------------------------------------
__global__ void clear_kernel(float4* __restrict__ agg) {
    int i = blockIdx.x * blockDim.x + threadIdx.x;
    if (i < N_NODES * HID / 4)
        agg[i] = make_float4(0.f, 0.f, 0.f, 0.f);
}

// ---------------------------------------------------------------------------
// Vectorized global reduction (sm_90+): 16B atomic add, no return value
// ---------------------------------------------------------------------------
__device__ __forceinline__ void red_add_v4(float* p, float4 v) {
    asm volatile("red.global.add.v4.f32 [%0], {%1, %2, %3, %4};"
                 :: "l"(p), "f"(v.x), "f"(v.y), "f"(v.z), "f"(v.w)
                 : "memory");
}

// ---------------------------------------------------------------------------
// Scatter: for each edge, agg[dst] += h[src] * w.
// 16 lanes per edge, one float4 per lane (HID=64 floats = 16 float4).
// Edge metadata staged through smem (coalesced loads).
// ---------------------------------------------------------------------------
__global__ __launch_bounds__(256)
void scatter_kernel(const float* __restrict__ h,
                    const float* __restrict__ ew,
                    float* __restrict__ agg) {
    constexpr int EPB = 64;  // edges per block; 256 threads -> 4 passes of 16 edges
    __shared__ int   ss[EPB];
    __shared__ int   sd[EPB];
    __shared__ float sw[EPB];

    int tid   = threadIdx.x;
    int ebase = blockIdx.x * EPB;
    if (tid < EPB) {
        ss[tid] = g_src[ebase + tid];
        sd[tid] = g_dst[ebase + tid];
        sw[tid] = ew[ebase + tid];
    }
    __syncthreads();

    int c  = tid & 15;   // float4 chunk within the 64-float row
    int eg = tid >> 4;   // edge group 0..15

    #pragma unroll
    for (int p = 0; p < EPB / 16; p++) {
        int   e  = p * 16 + eg;
        int   s  = ss[e];
        int   d  = sd[e];
        float wt = sw[e];
        float4 v = ((const float4*)h)[(size_t)s * (HID / 4) + c];
        v.x *= wt; v.y *= wt; v.z *= wt; v.w *= wt;
        red_add_v4(agg + (size_t)d * HID + c * 4, v);
    }
}

// ---------------------------------------------------------------------------
// Dense GEMM: out[n, :NC] = act( (in[n] (+ agg[n])) @ W[K,NC] + b )
// W resident in smem. Each thread owns 4 output columns (float4 acc),
// so one LDS.128 of W per 4 FMAs and one broadcast LDG.128 of the row per 4 k.
// ---------------------------------------------------------------------------
template<int K, int NC, bool RELU, bool ADD_AGG>
__global__ __launch_bounds__(256)
void gemm_kernel(const float* __restrict__ in, const float* __restrict__ agg,
                 const float* __restrict__ W, const float* __restrict__ b,
                 float* __restrict__ out) {
    constexpr int TPN    = NC / 4;    // threads per node
    constexpr int GROUPS = 256 / TPN; // nodes processed per pass
    constexpr int NPB    = 64;        // nodes per block

    __shared__ __align__(16) float Ws[K * NC];
    __shared__ __align__(16) float bs[NC];

    int tid = threadIdx.x;
    for (int i = tid; i < K * NC / 4; i += 256)
        ((float4*)Ws)[i] = ((const float4*)W)[i];
    if (tid < NC) bs[tid] = b[tid];
    __syncthreads();

    int cg    = tid % TPN;
    int grp   = tid / TPN;
    int node0 = blockIdx.x * NPB;

    for (int n = node0 + grp; n < node0 + NPB && n < N_NODES; n += GROUPS) {
        const float4* row  = (const float4*)(in + (size_t)n * K);
        const float4* arow = (const float4*)(agg + (size_t)n * K);
        float4 acc = ((const float4*)bs)[cg];

        #pragma unroll
        for (int k4 = 0; k4 < K / 4; k4++) {
            float4 xv = row[k4];
            if (ADD_AGG) {
                float4 av = arow[k4];
                xv.x += av.x; xv.y += av.y; xv.z += av.z; xv.w += av.w;
            }
            const float4* wr = (const float4*)Ws + (k4 * 4) * TPN + cg;
            float4 w0 = wr[0 * TPN];
            float4 w1 = wr[1 * TPN];
            float4 w2 = wr[2 * TPN];
            float4 w3 = wr[3 * TPN];
            acc.x += xv.x * w0.x + xv.y * w1.x + xv.z * w2.x + xv.w * w3.x;
            acc.y += xv.x * w0.y + xv.y * w1.y + xv.z * w2.y + xv.w * w3.y;
            acc.z += xv.x * w0.z + xv.y * w1.z + xv.z * w2.z + xv.w * w3.z;
            acc.w += xv.x * w0.w + xv.y * w1.w + xv.z * w2.w + xv.w * w3.w;
        }
        if (RELU) {
            acc.x = fmaxf(acc.x, 0.f);
            acc.y = fmaxf(acc.y, 0.f);
            acc.z = fmaxf(acc.z, 0.f);
            acc.w = fmaxf(acc.w, 0.f);
        }
        ((float4*)(out + (size_t)n * NC))[cg] = acc;
    }
}

// ---------------------------------------------------------------------------
// Launch
// ---------------------------------------------------------------------------
extern "C" void kernel_launch(void* const* d_in, const int* in_sizes, int n_in,
                              void* d_out, int out_size) {
    const float* x     = (const float*)d_in[0];
    const void*  ei    = d_in[1];
    const float* ew    = (const float*)d_in[2];
    const float* W_in  = (const float*)d_in[3];
    const float* b_in  = (const float*)d_in[4];
    const float* W_g   = (const float*)d_in[5];
    const float* b_g   = (const float*)d_in[6];
    const float* W_out = (const float*)d_in[7];
    const float* b_out = (const float*)d_in[8];
    float*       out   = (float*)d_out;

    float *hA, *hB, *agg;
    cudaGetSymbolAddress((void**)&hA,  g_hA);
    cudaGetSymbolAddress((void**)&hB,  g_hB);
    cudaGetSymbolAddress((void**)&agg, g_agg);

    const int node_blocks = (N_NODES + 63) / 64;      // 1563
    const int edge_blocks = N_EDGES / 64;             // 50000

    detect_kernel<<<1, 32>>>((const int*)ei);
    prep_edges_kernel<<<(N_EDGES + 255) / 256, 256>>>(ei);

    gemm_kernel<IN_DIM, HID, false, false><<<node_blocks, 256>>>(
        x, nullptr, W_in, b_in, hA);

    float* cur = hA;
    float* nxt = hB;
    for (int l = 0; l < N_LAYERS; l++) {
        clear_kernel<<<(N_NODES * HID / 4 + 255) / 256, 256>>>((float4*)agg);
        scatter_kernel<<<edge_blocks, 256>>>(cur, ew, agg);
        gemm_kernel<HID, HID, true, true><<<node_blocks, 256>>>(
            cur, agg, W_g + (size_t)l * HID * HID, b_g + (size_t)l * HID, nxt);
        float* t = cur; cur = nxt; nxt = t;
    }

    gemm_kernel<HID, OUT_DIM, false, false><<<node_blocks, 256>>>(
        cur, nullptr, W_out, b_out, out);
}

// round 3
// speedup vs baseline: 1.2435x; 1.2435x over previous
#include <cuda_runtime.h>

#define N_NODES 100000
#define N_EDGES 3200000
#define IN_DIM 128
#define HID 64
#define OUT_DIM 32
#define N_LAYERS 3

#define NBLK ((N_NODES + 255) / 256)   // 391 scan blocks

// Scratch: device globals (alloc-free, graph-capture safe)
__device__ float g_hA[N_NODES * HID];
__device__ float g_hB[N_NODES * HID];
__device__ float g_hsum[N_NODES * HID];
__device__ int2  g_es[N_EDGES];          // {src, weight_bits} sorted by dst
__device__ int   g_cnt[N_NODES];
__device__ int   g_rowptr[N_NODES];
__device__ int   g_ofs[N_NODES];
__device__ int   g_bsum[NBLK];
__device__ int   g_boff[NBLK];
__device__ int   g_is64;

// ---------------------------------------------------------------------------
// Detect edge_index dtype. int64 values < 2^31 => odd 32-bit words are 0.
// ---------------------------------------------------------------------------
__global__ void detect_kernel(const int* __restrict__ ei_raw) {
    if (threadIdx.x == 0 && blockIdx.x == 0) {
        int is64 = 1;
        for (int i = 0; i < 64; i++)
            if (ei_raw[2 * i + 1] != 0) { is64 = 0; break; }
        g_is64 = is64;
    }
}

__device__ __forceinline__ int load_idx(const void* ei, long long pos) {
    if (g_is64) return (int)((const long long*)ei)[pos];
    return ((const int*)ei)[pos];
}

// ---------------------------------------------------------------------------
// Zero the per-node counters (must run every call: graph replays everything)
// ---------------------------------------------------------------------------
__global__ void zero_cnt_kernel() {
    int i = blockIdx.x * blockDim.x + threadIdx.x;
    if (i < N_NODES) g_cnt[i] = 0;
}

// ---------------------------------------------------------------------------
// Histogram of dst
// ---------------------------------------------------------------------------
__global__ void hist_kernel(const void* __restrict__ ei) {
    int i = blockIdx.x * blockDim.x + threadIdx.x;
    if (i < N_EDGES) atomicAdd(&g_cnt[load_idx(ei, (long long)N_EDGES + i)], 1);
}

// ---------------------------------------------------------------------------
// 3-phase exclusive scan of g_cnt -> g_rowptr (and working copy g_ofs)
// ---------------------------------------------------------------------------
__global__ void scan1_kernel() {   // per-block reduce
    __shared__ int s[256];
    int i = blockIdx.x * 256 + threadIdx.x;
    s[threadIdx.x] = (i < N_NODES) ? g_cnt[i] : 0;
    __syncthreads();
    for (int off = 128; off > 0; off >>= 1) {
        if (threadIdx.x < off) s[threadIdx.x] += s[threadIdx.x + off];
        __syncthreads();
    }
    if (threadIdx.x == 0) g_bsum[blockIdx.x] = s[0];
}

__global__ void scan2_kernel() {   // scan the 391 block sums (1 block, 512 thr)
    __shared__ int s[512];
    int t = threadIdx.x;
    int v0 = (t < NBLK) ? g_bsum[t] : 0;
    s[t] = v0;
    __syncthreads();
    for (int off = 1; off < 512; off <<= 1) {
        int v = (t >= off) ? s[t - off] : 0;
        __syncthreads();
        s[t] += v;
        __syncthreads();
    }
    if (t < NBLK) g_boff[t] = s[t] - v0;   // exclusive
}

__global__ void scan3_kernel() {   // block-local exclusive scan + offset
    __shared__ int s[256];
    int t = threadIdx.x;
    int i = blockIdx.x * 256 + t;
    int v0 = (i < N_NODES) ? g_cnt[i] : 0;
    s[t] = v0;
    __syncthreads();
    for (int off = 1; off < 256; off <<= 1) {
        int v = (t >= off) ? s[t - off] : 0;
        __syncthreads();
        s[t] += v;
        __syncthreads();
    }
    if (i < N_NODES) {
        int start = g_boff[blockIdx.x] + s[t] - v0;
        g_rowptr[i] = start;
        g_ofs[i]    = start;
    }
}

// ---------------------------------------------------------------------------
// Bucket-place edges by dst: es[p] = {src, weight_bits}
// ---------------------------------------------------------------------------
__global__ void sort_kernel(const void* __restrict__ ei,
                            const float* __restrict__ ew) {
    int i = blockIdx.x * blockDim.x + threadIdx.x;
    if (i >= N_EDGES) return;
    int src = load_idx(ei, i);
    int dst = load_idx(ei, (long long)N_EDGES + i);
    int p = atomicAdd(&g_ofs[dst], 1);
    g_es[p] = make_int2(src, __float_as_int(ew[i]));
}

// ---------------------------------------------------------------------------
// Gather-aggregate: hsum[n] = h[n] + sum_{e in CSR row n} h[src_e] * w_e
// One 16-lane group per node; lane owns one float4 chunk of the 64-float row.
// 4-way edge unroll for MLP.
// ---------------------------------------------------------------------------
__global__ __launch_bounds__(256)
void gather_kernel(const float* __restrict__ h, float* __restrict__ hsum) {
    int lane = threadIdx.x & 15;
    int n = (blockIdx.x * 256 + threadIdx.x) >> 4;
    if (n >= N_NODES) return;

    int beg = g_rowptr[n];
    int cnt = g_cnt[n];
    int end = beg + cnt;

    const float4* h4 = (const float4*)h;
    float4 a0 = make_float4(0.f, 0.f, 0.f, 0.f);
    float4 a1 = make_float4(0.f, 0.f, 0.f, 0.f);

    int e = beg;
    for (; e + 3 < end; e += 4) {
        int2 m0 = g_es[e];
        int2 m1 = g_es[e + 1];
        int2 m2 = g_es[e + 2];
        int2 m3 = g_es[e + 3];
        float4 v0 = h4[(size_t)m0.x * 16 + lane];
        float4 v1 = h4[(size_t)m1.x * 16 + lane];
        float4 v2 = h4[(size_t)m2.x * 16 + lane];
        float4 v3 = h4[(size_t)m3.x * 16 + lane];
        float w0 = __int_as_float(m0.y), w1 = __int_as_float(m1.y);
        float w2 = __int_as_float(m2.y), w3 = __int_as_float(m3.y);
        a0.x += v0.x * w0; a0.y += v0.y * w0; a0.z += v0.z * w0; a0.w += v0.w * w0;
        a1.x += v1.x * w1; a1.y += v1.y * w1; a1.z += v1.z * w1; a1.w += v1.w * w1;
        a0.x += v2.x * w2; a0.y += v2.y * w2; a0.z += v2.z * w2; a0.w += v2.w * w2;
        a1.x += v3.x * w3; a1.y += v3.y * w3; a1.z += v3.z * w3; a1.w += v3.w * w3;
    }
    for (; e < end; e++) {
        int2 m = g_es[e];
        float w = __int_as_float(m.y);
        float4 v = h4[(size_t)m.x * 16 + lane];
        a0.x += v.x * w; a0.y += v.y * w; a0.z += v.z * w; a0.w += v.w * w;
    }

    float4 hv = h4[(size_t)n * 16 + lane];
    a0.x += a1.x + hv.x;
    a0.y += a1.y + hv.y;
    a0.z += a1.z + hv.z;
    a0.w += a1.w + hv.w;
    ((float4*)hsum)[(size_t)n * 16 + lane] = a0;
}

// ---------------------------------------------------------------------------
// Dense GEMM: out[n, :NC] = act( in[n] @ W[K,NC] + b ), W in smem.
// ---------------------------------------------------------------------------
template<int K, int NC, bool RELU>
__global__ __launch_bounds__(256)
void gemm_kernel(const float* __restrict__ in,
                 const float* __restrict__ W, const float* __restrict__ b,
                 float* __restrict__ out) {
    constexpr int TPN    = NC / 4;
    constexpr int GROUPS = 256 / TPN;
    constexpr int NPB    = 64;

    __shared__ __align__(16) float Ws[K * NC];
    __shared__ __align__(16) float bs[NC];

    int tid = threadIdx.x;
    for (int i = tid; i < K * NC / 4; i += 256)
        ((float4*)Ws)[i] = ((const float4*)W)[i];
    if (tid < NC) bs[tid] = b[tid];
    __syncthreads();

    int cg    = tid % TPN;
    int grp   = tid / TPN;
    int node0 = blockIdx.x * NPB;

    for (int n = node0 + grp; n < node0 + NPB && n < N_NODES; n += GROUPS) {
        const float4* row = (const float4*)(in + (size_t)n * K);
        float4 acc = ((const float4*)bs)[cg];

        #pragma unroll
        for (int k4 = 0; k4 < K / 4; k4++) {
            float4 xv = row[k4];
            const float4* wr = (const float4*)Ws + (k4 * 4) * TPN + cg;
            float4 w0 = wr[0 * TPN];
            float4 w1 = wr[1 * TPN];
            float4 w2 = wr[2 * TPN];
            float4 w3 = wr[3 * TPN];
            acc.x += xv.x * w0.x + xv.y * w1.x + xv.z * w2.x + xv.w * w3.x;
            acc.y += xv.x * w0.y + xv.y * w1.y + xv.z * w2.y + xv.w * w3.y;
            acc.z += xv.x * w0.z + xv.y * w1.z + xv.z * w2.z + xv.w * w3.z;
            acc.w += xv.x * w0.w + xv.y * w1.w + xv.z * w2.w + xv.w * w3.w;
        }
        if (RELU) {
            acc.x = fmaxf(acc.x, 0.f);
            acc.y = fmaxf(acc.y, 0.f);
            acc.z = fmaxf(acc.z, 0.f);
            acc.w = fmaxf(acc.w, 0.f);
        }
        ((float4*)(out + (size_t)n * NC))[cg] = acc;
    }
}

// ---------------------------------------------------------------------------
// Launch
// ---------------------------------------------------------------------------
extern "C" void kernel_launch(void* const* d_in, const int* in_sizes, int n_in,
                              void* d_out, int out_size) {
    const float* x     = (const float*)d_in[0];
    const void*  ei    = d_in[1];
    const float* ew    = (const float*)d_in[2];
    const float* W_in  = (const float*)d_in[3];
    const float* b_in  = (const float*)d_in[4];
    const float* W_g   = (const float*)d_in[5];
    const float* b_g   = (const float*)d_in[6];
    const float* W_out = (const float*)d_in[7];
    const float* b_out = (const float*)d_in[8];
    float*       out   = (float*)d_out;

    float *hA, *hB, *hsum;
    cudaGetSymbolAddress((void**)&hA,   g_hA);
    cudaGetSymbolAddress((void**)&hB,   g_hB);
    cudaGetSymbolAddress((void**)&hsum, g_hsum);

    const int node_blocks   = (N_NODES + 63) / 64;      // gemm grid
    const int edge_blocks   = (N_EDGES + 255) / 256;
    const int gather_blocks = (N_NODES * 16 + 255) / 256;

    // CSR build (once per call)
    detect_kernel<<<1, 32>>>((const int*)ei);
    zero_cnt_kernel<<<NBLK, 256>>>();
    hist_kernel<<<edge_blocks, 256>>>(ei);
    scan1_kernel<<<NBLK, 256>>>();
    scan2_kernel<<<1, 512>>>();
    scan3_kernel<<<NBLK, 256>>>();
    sort_kernel<<<edge_blocks, 256>>>(ei, ew);

    // input projection
    gemm_kernel<IN_DIM, HID, false><<<node_blocks, 256>>>(x, W_in, b_in, hA);

    float* cur = hA;
    float* nxt = hB;
    for (int l = 0; l < N_LAYERS; l++) {
        gather_kernel<<<gather_blocks, 256>>>(cur, hsum);
        gemm_kernel<HID, HID, true><<<node_blocks, 256>>>(
            hsum, W_g + (size_t)l * HID * HID, b_g + (size_t)l * HID, nxt);
        float* t = cur; cur = nxt; nxt = t;
    }

    gemm_kernel<HID, OUT_DIM, false><<<node_blocks, 256>>>(cur, W_out, b_out, out);
}